// round 1
// baseline (speedup 1.0000x reference)
#include <cuda_runtime.h>
#include <cstdint>

#define N_ROWS 65536
#define DIM    256
#define KCODES 1024
#define TM     128   // rows per CTA tile
#define TKC    128   // codes per tile
#define TD     16    // D-chunk
#define NBLK   (N_ROWS / TM)   // 512

__device__ float  g_znorm[N_ROWS];
__device__ float  g_enorm[KCODES];
__device__ double g_partial[NBLK];

// --------------------------------------------------------------------------
// Kernel 1: row norms for z (65536 rows) and embeddings (1024 rows).
// One warp per row: 8 floats/lane (2x float4), warp shuffle reduce.
// --------------------------------------------------------------------------
__global__ void norms_kernel(const float* __restrict__ z,
                             const float* __restrict__ emb) {
    int w    = blockIdx.x * 8 + (threadIdx.x >> 5);
    int lane = threadIdx.x & 31;
    if (w >= N_ROWS + KCODES) return;
    const float* src = (w < N_ROWS) ? (z + (size_t)w * DIM)
                                    : (emb + (size_t)(w - N_ROWS) * DIM);
    float4 v1 = *(const float4*)(src + lane * 8);
    float4 v2 = *(const float4*)(src + lane * 8 + 4);
    float s = v1.x*v1.x + v1.y*v1.y + v1.z*v1.z + v1.w*v1.w
            + v2.x*v2.x + v2.y*v2.y + v2.z*v2.z + v2.w*v2.w;
    #pragma unroll
    for (int off = 16; off > 0; off >>= 1)
        s += __shfl_xor_sync(0xffffffffu, s, off);
    if (lane == 0) {
        if (w < N_ROWS) g_znorm[w] = s;
        else            g_enorm[w - N_ROWS] = s;
    }
}

// --------------------------------------------------------------------------
// Kernel 2: fused score-GEMM + argmin + gather + output + loss partial.
// CTA = 128 z-rows. Loops over 8 code tiles of 128; smem-tiled SGEMM with
// 8x8 register fragments (16x16 thread grid). Distances follow the reference
// formula exactly: d = (||z||^2 + ||e||^2) - 2*dot, fp32 at each step.
// Argmin: strict '<' scanning ascending code index (first-index tie-break);
// cross-thread reduce ties break toward smaller index.
// --------------------------------------------------------------------------
__global__ __launch_bounds__(256, 2)
void vq_main(const float* __restrict__ z,
             const float* __restrict__ emb,
             float* __restrict__ out) {
    __shared__ float As[TD][TM + 4];
    __shared__ float Bs[TD][TKC + 4];
    __shared__ int   s_best[TM];
    __shared__ float red[256];

    const int tid = threadIdx.x;
    const int tx  = tid & 15;       // code-fragment group
    const int ty  = tid >> 4;       // row-fragment group
    const int r0  = blockIdx.x * TM;

    float znr[8];
    #pragma unroll
    for (int i = 0; i < 8; i++) znr[i] = g_znorm[r0 + ty * 8 + i];

    float bestv[8];
    int   besti[8];
    #pragma unroll
    for (int i = 0; i < 8; i++) { bestv[i] = 3.4e38f; besti[i] = 0; }

    for (int c0 = 0; c0 < KCODES; c0 += TKC) {
        float acc[8][8];
        #pragma unroll
        for (int i = 0; i < 8; i++)
            #pragma unroll
            for (int j = 0; j < 8; j++) acc[i][j] = 0.0f;

        for (int d0 = 0; d0 < DIM; d0 += TD) {
            // Stage A (z tile) and B (embedding tile): 512 float4 each.
            #pragma unroll
            for (int q = 0; q < 2; q++) {
                int s   = tid + q * 256;
                int row = s >> 2;
                int dp  = (s & 3) * 4;
                float4 va = *(const float4*)(z + (size_t)(r0 + row) * DIM + d0 + dp);
                As[dp + 0][row] = va.x; As[dp + 1][row] = va.y;
                As[dp + 2][row] = va.z; As[dp + 3][row] = va.w;
                float4 vb = *(const float4*)(emb + (size_t)(c0 + row) * DIM + d0 + dp);
                Bs[dp + 0][row] = vb.x; Bs[dp + 1][row] = vb.y;
                Bs[dp + 2][row] = vb.z; Bs[dp + 3][row] = vb.w;
            }
            __syncthreads();
            #pragma unroll
            for (int dd = 0; dd < TD; dd++) {
                float a[8], b[8];
                *(float4*)(a + 0) = *(const float4*)(&As[dd][ty * 8 + 0]);
                *(float4*)(a + 4) = *(const float4*)(&As[dd][ty * 8 + 4]);
                *(float4*)(b + 0) = *(const float4*)(&Bs[dd][tx * 8 + 0]);
                *(float4*)(b + 4) = *(const float4*)(&Bs[dd][tx * 8 + 4]);
                #pragma unroll
                for (int i = 0; i < 8; i++)
                    #pragma unroll
                    for (int j = 0; j < 8; j++)
                        acc[i][j] += a[i] * b[j];
            }
            __syncthreads();
        }

        // scores + running argmin for this code tile
        float en[8];
        #pragma unroll
        for (int j = 0; j < 8; j++) en[j] = g_enorm[c0 + tx * 8 + j];
        #pragma unroll
        for (int i = 0; i < 8; i++) {
            #pragma unroll
            for (int j = 0; j < 8; j++) {
                float d = (znr[i] + en[j]) - 2.0f * acc[i][j];
                int   c = c0 + tx * 8 + j;
                if (d < bestv[i]) { bestv[i] = d; besti[i] = c; }
            }
        }
    }

    // Cross-thread argmin: 16 tx-threads per row group are a contiguous
    // half-warp (tid = ty*16+tx) -> width-16 shuffle reduce.
    #pragma unroll
    for (int i = 0; i < 8; i++) {
        float v  = bestv[i];
        int   ix = besti[i];
        #pragma unroll
        for (int off = 8; off > 0; off >>= 1) {
            float v2 = __shfl_down_sync(0xffffffffu, v,  off, 16);
            int   i2 = __shfl_down_sync(0xffffffffu, ix, off, 16);
            if (v2 < v || (v2 == v && i2 < ix)) { v = v2; ix = i2; }
        }
        if (tx == 0) s_best[ty * 8 + i] = ix;
    }
    __syncthreads();

    // Epilogue: out = z + (e_best - z) (reference ST arithmetic), loss partial.
    float lsum = 0.0f;
    for (int s = tid; s < TM * (DIM / 4); s += 256) {
        int row = s >> 6;
        int dp  = (s & 63) * 4;
        const float4 zv = *(const float4*)(z + (size_t)(r0 + row) * DIM + dp);
        int c = s_best[row];
        const float4 ev = *(const float4*)(emb + (size_t)c * DIM + dp);
        float dx = ev.x - zv.x, dy = ev.y - zv.y, dz_ = ev.z - zv.z, dw = ev.w - zv.w;
        float4 o;
        o.x = zv.x + dx; o.y = zv.y + dy; o.z = zv.z + dz_; o.w = zv.w + dw;
        *(float4*)(out + (size_t)(r0 + row) * DIM + dp) = o;
        lsum += dx*dx + dy*dy + dz_*dz_ + dw*dw;
    }
    red[tid] = lsum;
    __syncthreads();
    for (int st = 128; st > 0; st >>= 1) {
        if (tid < st) red[tid] += red[tid + st];
        __syncthreads();
    }
    if (tid == 0) g_partial[blockIdx.x] = (double)red[0];
}

// --------------------------------------------------------------------------
// Kernel 3: deterministic tree-sum of per-block partials; write loss scalar.
// loss = codebook + BETA*commitment = m + 0.25*m (forward values identical).
// --------------------------------------------------------------------------
__global__ void finalize_kernel(float* __restrict__ out) {
    __shared__ double sd[NBLK];
    int t = threadIdx.x;
    sd[t] = g_partial[t];
    __syncthreads();
    for (int st = NBLK / 2; st > 0; st >>= 1) {
        if (t < st) sd[t] += sd[t + st];
        __syncthreads();
    }
    if (t == 0) {
        float m = (float)(sd[0] / ((double)N_ROWS * (double)DIM));
        out[(size_t)N_ROWS * DIM] = m + 0.25f * m;
    }
}

extern "C" void kernel_launch(void* const* d_in, const int* in_sizes, int n_in,
                              void* d_out, int out_size) {
    const float* z   = (const float*)d_in[0];
    const float* emb = (const float*)d_in[1];
    float* out = (float*)d_out;

    norms_kernel<<<(N_ROWS + KCODES) / 8, 256>>>(z, emb);
    vq_main<<<NBLK, 256>>>(z, emb, out);
    finalize_kernel<<<1, NBLK>>>(out);
}